// round 2
// baseline (speedup 1.0000x reference)
#include <cuda_runtime.h>
#include <math.h>

// ---------------- problem constants (fixed shapes) ----------------
#define BATCH 64
#define NC 1024
#define NT 1024
#define H 512
#define NP (BATCH*(NC+NT))   // 131072 total points
#define NCTX (BATCH*NC)      // 65536 context rows
#define NRP1 513             // R+1
#define LD 520               // row stride for cov (pad for alignment)
#define COVSTRIDE (NRP1*LD)  // per-batch cov floats

// ---------------- scratch (static device globals; no allocation) ----------------
__device__ float g_bufA[(size_t)NP * H];          // ping
__device__ float g_bufB[(size_t)NP * H];          // pong / final features
__device__ float g_cov[(size_t)BATCH * COVSTRIDE];
__device__ float g_xty[BATCH * LD];               // rhs -> solution in place
__device__ float g_yc[BATCH * NC];
__device__ float g_mean[BATCH];
__device__ float g_std[BATCH];

// ---------------- 1) per-batch mean/std (ddof=1) + normalize ----------------
__global__ void __launch_bounds__(256) stats_kernel(const float* __restrict__ y) {
    const int b = blockIdx.x, tid = threadIdx.x;
    __shared__ float red[256];
    float v[4];
#pragma unroll
    for (int t = 0; t < 4; t++) v[t] = y[b * NC + tid + t * 256];
    float s = v[0] + v[1] + v[2] + v[3];
    red[tid] = s; __syncthreads();
    for (int st = 128; st > 0; st >>= 1) { if (tid < st) red[tid] += red[tid + st]; __syncthreads(); }
    const float mean = red[0] * (1.0f / NC);
    __syncthreads();
    float q = 0.f;
#pragma unroll
    for (int t = 0; t < 4; t++) { float d = v[t] - mean; q += d * d; }
    red[tid] = q; __syncthreads();
    for (int st = 128; st > 0; st >>= 1) { if (tid < st) red[tid] += red[tid + st]; __syncthreads(); }
    const float var = red[0] * (1.0f / (NC - 1));
    const float sd = sqrtf(var);
    const float inv = 1.0f / sd;
#pragma unroll
    for (int t = 0; t < 4; t++) g_yc[b * NC + tid + t * 256] = (v[t] - mean) * inv;
    if (tid == 0) { g_mean[b] = mean; g_std[b] = sd; }
}

// ---------------- 2) SIREN layer 0 (XD=1, elementwise) ----------------
__global__ void __launch_bounds__(256) layer0_kernel(const float* __restrict__ xc,
                                                     const float* __restrict__ xt,
                                                     const float* __restrict__ W0,
                                                     const float* __restrict__ b0) {
    const int idx = blockIdx.x * 256 + threadIdx.x;   // one per 4 outputs
    const int p = idx >> 7;                            // H/4 = 128 groups per point
    const int j4 = (idx & 127) << 2;
    const float x = (p < NCTX) ? xc[p] : xt[p - NCTX];
    const float4 w = *(const float4*)(W0 + j4);
    const float4 bb = *(const float4*)(b0 + j4);
    float4 o;
    o.x = sinf(30.0f * fmaf(x, w.x, bb.x));
    o.y = sinf(30.0f * fmaf(x, w.y, bb.y));
    o.z = sinf(30.0f * fmaf(x, w.z, bb.z));
    o.w = sinf(30.0f * fmaf(x, w.w, bb.w));
    *(float4*)(g_bufA + (size_t)p * H + j4) = o;
}

// ---------------- 3) tiled SGEMM: C = act(A @ W + b), A:[NP,512] W:[512,512] ----------------
template <int SIN>
__global__ void __launch_bounds__(256) gemm_kernel(const float* __restrict__ W,
                                                   const float* __restrict__ bias,
                                                   int dir) {
    const float* __restrict__ A = dir ? g_bufB : g_bufA;
    float* __restrict__ C = dir ? g_bufA : g_bufB;
    __shared__ float As[8][132];   // padded to dodge store conflicts
    __shared__ float Bs[8][128];
    const int tid = threadIdx.x;
    const int tx = tid & 15, ty = tid >> 4;
    const int m0 = blockIdx.y << 7, n0 = blockIdx.x << 7;
    const int ar = tid >> 1, ac = (tid & 1) << 2;
    const int brr = tid >> 5, bc = (tid & 31) << 2;
    float acc[8][8];
#pragma unroll
    for (int i = 0; i < 8; i++) {
#pragma unroll
        for (int j = 0; j < 8; j++) acc[i][j] = 0.0f;
    }
    const float* Ap = A + (size_t)(m0 + ar) * H + ac;
    const float* Wp = W + (size_t)brr * H + n0 + bc;
    for (int k0 = 0; k0 < H; k0 += 8) {
        const float4 av = *(const float4*)(Ap + k0);
        const float4 bv = *(const float4*)(Wp + (size_t)k0 * H);
        As[ac + 0][ar] = av.x; As[ac + 1][ar] = av.y;
        As[ac + 2][ar] = av.z; As[ac + 3][ar] = av.w;
        *(float4*)&Bs[brr][bc] = bv;
        __syncthreads();
#pragma unroll
        for (int kk = 0; kk < 8; kk++) {
            float a[8], bq[8];
            *(float4*)&a[0] = *(const float4*)&As[kk][ty << 3];
            *(float4*)&a[4] = *(const float4*)&As[kk][(ty << 3) + 4];
            *(float4*)&bq[0] = *(const float4*)&Bs[kk][tx << 3];
            *(float4*)&bq[4] = *(const float4*)&Bs[kk][(tx << 3) + 4];
#pragma unroll
            for (int i = 0; i < 8; i++) {
#pragma unroll
                for (int j = 0; j < 8; j++) acc[i][j] = fmaf(a[i], bq[j], acc[i][j]);
            }
        }
        __syncthreads();
    }
    float bs[8];
#pragma unroll
    for (int j = 0; j < 8; j++) bs[j] = bias[n0 + (tx << 3) + j];
#pragma unroll
    for (int i = 0; i < 8; i++) {
        float* Crow = C + (size_t)(m0 + (ty << 3) + i) * H + n0 + (tx << 3);
        float vout[8];
#pragma unroll
        for (int j = 0; j < 8; j++) {
            float v = acc[i][j] + bs[j];
            vout[j] = SIN ? sinf(v) : v;
        }
        *(float4*)Crow = *(float4*)&vout[0];
        *(float4*)(Crow + 4) = *(float4*)&vout[4];
    }
}

// ---------------- 4) per-batch cov = F^T F (512x512 core block) ----------------
__global__ void __launch_bounds__(256) cov_kernel() {
    const int b = blockIdx.z;
    const float* __restrict__ F = g_bufB + (size_t)b * NC * H;   // context features
    float* __restrict__ Cc = g_cov + (size_t)b * COVSTRIDE;
    __shared__ float Fa[8][128];
    __shared__ float Fb[8][128];
    const int tid = threadIdx.x;
    const int tx = tid & 15, ty = tid >> 4;
    const int m0 = blockIdx.y << 7, n0 = blockIdx.x << 7;
    const int kr = tid >> 5, c4 = (tid & 31) << 2;
    float acc[8][8];
#pragma unroll
    for (int i = 0; i < 8; i++) {
#pragma unroll
        for (int j = 0; j < 8; j++) acc[i][j] = 0.0f;
    }
    for (int k0 = 0; k0 < NC; k0 += 8) {
        const float* Frow = F + (size_t)(k0 + kr) * H;
        *(float4*)&Fa[kr][c4] = *(const float4*)(Frow + m0 + c4);
        *(float4*)&Fb[kr][c4] = *(const float4*)(Frow + n0 + c4);
        __syncthreads();
#pragma unroll
        for (int kk = 0; kk < 8; kk++) {
            float a[8], bq[8];
            *(float4*)&a[0] = *(const float4*)&Fa[kk][ty << 3];
            *(float4*)&a[4] = *(const float4*)&Fa[kk][(ty << 3) + 4];
            *(float4*)&bq[0] = *(const float4*)&Fb[kk][tx << 3];
            *(float4*)&bq[4] = *(const float4*)&Fb[kk][(tx << 3) + 4];
#pragma unroll
            for (int i = 0; i < 8; i++) {
#pragma unroll
                for (int j = 0; j < 8; j++) acc[i][j] = fmaf(a[i], bq[j], acc[i][j]);
            }
        }
        __syncthreads();
    }
#pragma unroll
    for (int i = 0; i < 8; i++) {
        float* Crow = Cc + (size_t)(m0 + (ty << 3) + i) * LD + n0 + (tx << 3);
        *(float4*)Crow = *(float4*)&acc[i][0];
        *(float4*)(Crow + 4) = *(float4*)&acc[i][4];
    }
}

// ---------------- 5) xty + cov borders (ones feature) + lambda*I ----------------
__global__ void __launch_bounds__(512) xty_border_kernel(const float* __restrict__ lnv) {
    const int b = blockIdx.x, tid = threadIdx.x;
    __shared__ float yc_s[NC];
    for (int i = tid; i < NC; i += 512) yc_s[i] = g_yc[b * NC + i];
    __syncthreads();
    const float* __restrict__ F = g_bufB + (size_t)b * NC * H;
    float s0 = 0.f, s1 = 0.f;
    for (int n = 0; n < NC; n++) {
        float f = F[(size_t)n * H + tid];
        s0 += f;
        s1 += f * yc_s[n];
    }
    const float lam = expf(lnv[0]);
    float* Cc = g_cov + (size_t)b * COVSTRIDE;
    g_xty[b * LD + tid] = s1;
    Cc[512 * LD + tid] = s0;                 // row 512 (needed by Cholesky, lower tri)
    Cc[(size_t)tid * LD + 512] = s0;         // symmetry (harmless)
    Cc[(size_t)tid * LD + tid] += lam;
    if (tid == 0) {
        float sy = 0.f;
        for (int n = 0; n < NC; n++) sy += yc_s[n];
        g_xty[b * LD + 512] = sy;
        Cc[512 * LD + 512] = (float)NC + lam;
    }
}

// ---------------- 6) in-place Cholesky (lower), one CTA per batch ----------------
__global__ void __launch_bounds__(1024) cholesky_kernel() {
    const int b = blockIdx.x;
    float* __restrict__ A = g_cov + (size_t)b * COVSTRIDE;
    __shared__ float colk[NRP1];
    __shared__ float sinv;
    const int tid = threadIdx.x;
    const int warp = tid >> 5, lane = tid & 31;
    for (int k = 0; k < NRP1; k++) {
        if (tid == 0) {
            float d = A[(size_t)k * LD + k];
            float sq = sqrtf(d);
            A[(size_t)k * LD + k] = sq;
            sinv = 1.0f / sq;
        }
        __syncthreads();
        const float inv = sinv;
        for (int i = k + 1 + tid; i < NRP1; i += 1024) {
            float v = A[(size_t)i * LD + k] * inv;
            A[(size_t)i * LD + k] = v;
            colk[i] = v;
        }
        __syncthreads();
        for (int i = k + 1 + warp; i < NRP1; i += 32) {
            const float Lik = colk[i];
            for (int j = k + 1 + lane; j <= i; j += 32)
                A[(size_t)i * LD + j] -= Lik * colk[j];
        }
        __syncthreads();
    }
}

// ---------------- 7) forward + backward triangular solve, one CTA per batch ----------------
__global__ void __launch_bounds__(512) solve_kernel() {
    const int b = blockIdx.x, tid = threadIdx.x;
    const float* __restrict__ L = g_cov + (size_t)b * COVSTRIDE;
    __shared__ float vs[NRP1];
    __shared__ float invd[NRP1];
    for (int i = tid; i < NRP1; i += 512) {
        vs[i] = g_xty[b * LD + i];
        invd[i] = 1.0f / L[(size_t)i * LD + i];
    }
    __syncthreads();
    // forward: L z = v   (axpy form; column reads)
    for (int k = 0; k < NRP1; k++) {
        if (tid == 0) vs[k] *= invd[k];
        __syncthreads();
        const float vk = vs[k];
        for (int i = k + 1 + tid; i < NRP1; i += 512)
            vs[i] -= L[(size_t)i * LD + k] * vk;
        __syncthreads();
    }
    // backward: L^T w = z (row reads)
    for (int k = NRP1 - 1; k >= 0; k--) {
        if (tid == 0) vs[k] *= invd[k];
        __syncthreads();
        const float wk = vs[k];
        for (int j = tid; j < k; j += 512)
            vs[j] -= L[(size_t)k * LD + j] * wk;
        __syncthreads();
    }
    for (int i = tid; i < NRP1; i += 512) g_xty[b * LD + i] = vs[i];
}

// ---------------- 8) predict: out = (tr @ w + w[512]) * std + mean ----------------
__global__ void __launch_bounds__(256) predict_kernel(float* __restrict__ out) {
    const int g = (blockIdx.x * 256 + threadIdx.x) >> 5;   // global row (warp per row)
    const int lane = threadIdx.x & 31;
    const int b = g >> 10;
    const float* __restrict__ tr = g_bufB + (size_t)(NCTX + g) * H;
    const float* __restrict__ w = g_xty + b * LD;
    float acc = 0.f;
#pragma unroll
    for (int t = lane; t < H; t += 32) acc = fmaf(tr[t], w[t], acc);
#pragma unroll
    for (int o = 16; o; o >>= 1) acc += __shfl_xor_sync(0xffffffffu, acc, o);
    if (lane == 0) out[g] = fmaf(acc + w[H], g_std[b], g_mean[b]);
}

// ---------------- launch ----------------
extern "C" void kernel_launch(void* const* d_in, const int* in_sizes, int n_in,
                              void* d_out, int out_size) {
    const float* x_ctx = (const float*)d_in[0];
    const float* y_ctx = (const float*)d_in[1];
    const float* x_tgt = (const float*)d_in[2];
    const float* W0 = (const float*)d_in[3];
    const float* b0 = (const float*)d_in[4];
    const float* W1 = (const float*)d_in[5];
    const float* b1 = (const float*)d_in[6];
    const float* W2 = (const float*)d_in[7];
    const float* b2 = (const float*)d_in[8];
    const float* Wr = (const float*)d_in[9];
    const float* br = (const float*)d_in[10];
    const float* lnv = (const float*)d_in[11];
    float* out = (float*)d_out;

    stats_kernel<<<BATCH, 256>>>(y_ctx);
    layer0_kernel<<<(NP * (H / 4)) / 256, 256>>>(x_ctx, x_tgt, W0, b0);          // -> bufA
    gemm_kernel<1><<<dim3(H / 128, NP / 128), 256>>>(W1, b1, /*dir=*/0);          // A -> B
    gemm_kernel<1><<<dim3(H / 128, NP / 128), 256>>>(W2, b2, /*dir=*/1);          // B -> A
    gemm_kernel<0><<<dim3(H / 128, NP / 128), 256>>>(Wr, br, /*dir=*/0);          // A -> B (features)
    cov_kernel<<<dim3(4, 4, BATCH), 256>>>();
    xty_border_kernel<<<BATCH, 512>>>(lnv);
    cholesky_kernel<<<BATCH, 1024>>>();
    solve_kernel<<<BATCH, 512>>>();
    predict_kernel<<<(NCTX / 8 + 0) / 1 / 1024 * 1024 == 0 ? 8192 : 8192, 256>>>(out);
}